// round 14
// baseline (speedup 1.0000x reference)
#include <cuda_runtime.h>
#include <cuda_bf16.h>

typedef unsigned long long u64;
typedef unsigned int u32;

// ---------------- scratch ----------------
__device__ float g_spart[256 * 16384];
__device__ float g_scores[16384];
__device__ float g_pe[1024];
__device__ float g_A[16384];             // A[d][e] = sum_g Wq[g,d] Wk[g,e]
__device__ float g_bv[128];
__device__ float g_u[128];
__device__ float g_w[128];
__device__ float g_cpart[16 * 16384];
__device__ float g_c[16384];
__device__ float g_alpha[128];
__device__ float g_beta[128];
__device__ float g_gamma;

// bf16 hi/lo tensors
__device__ __align__(16) __nv_bfloat16 g_Yhi[16777216];
__device__ __align__(16) __nv_bfloat16 g_Ylo[16777216];
__device__ __align__(16) __nv_bfloat16 g_Zhi[16777216];
__device__ __align__(16) __nv_bfloat16 g_Zlo[16777216];
// padded operand images [128][136]
__device__ __align__(16) __nv_bfloat16 g_Aophi[17408];
__device__ __align__(16) __nv_bfloat16 g_Aoplo[17408];
__device__ __align__(16) __nv_bfloat16 g_Wvophi[17408];
__device__ __align__(16) __nv_bfloat16 g_Wvoplo[17408];
__device__ __align__(16) __nv_bfloat16 g_athi[17408];   // attn hi [128][136]
__device__ __align__(16) __nv_bfloat16 g_atlo[17408];   // attn lo

// ---------------- helpers ----------------
__device__ __forceinline__ u32 smem_u32(const void* p) {
    u32 a; asm("{ .reg .u64 t; cvta.to.shared.u64 t, %1; cvt.u32.u64 %0, t; }" : "=r"(a) : "l"(p));
    return a;
}
__device__ __forceinline__ void cp16(u32 dst, const void* src) {
    asm volatile("cp.async.cg.shared.global [%0], [%1], 16;" :: "r"(dst), "l"(src));
}
__device__ __forceinline__ void cp_commit() { asm volatile("cp.async.commit_group;" ::: "memory"); }
template<int N> __device__ __forceinline__ void cp_wait() {
    asm volatile("cp.async.wait_group %0;" :: "n"(N) : "memory");
}

__device__ __forceinline__ void mma16816(float* c, const u32* a, const u32* b) {
    asm volatile("mma.sync.aligned.m16n8k16.row.col.f32.bf16.bf16.f32 "
        "{%0,%1,%2,%3}, {%4,%5,%6,%7}, {%8,%9}, {%0,%1,%2,%3};"
        : "+f"(c[0]), "+f"(c[1]), "+f"(c[2]), "+f"(c[3])
        : "r"(a[0]), "r"(a[1]), "r"(a[2]), "r"(a[3]), "r"(b[0]), "r"(b[1]));
}

__device__ __forceinline__ void pack_hilo(float a, float b, u32& hp, u32& lp) {
    __nv_bfloat16 ha = __float2bfloat16(a), hb = __float2bfloat16(b);
    float ra = a - __bfloat162float(ha), rb = b - __bfloat162float(hb);
    __nv_bfloat16 la = __float2bfloat16(ra), lb = __float2bfloat16(rb);
    hp = (u32)__bfloat16_as_ushort(ha) | ((u32)__bfloat16_as_ushort(hb) << 16);
    lp = (u32)__bfloat16_as_ushort(la) | ((u32)__bfloat16_as_ushort(lb) << 16);
}

// fused tri-product: C += Ah*Bh^T + Ah*Bl^T + Al*Bh^T  (fragments loaded once)
template<int KC, int SW>
__device__ __forceinline__ void gemm_prod3(float (&acc)[2][8][4],
                                           const u32* Ah, const u32* Al,
                                           const u32* Bh, const u32* Bl,
                                           int wm, int wn, int g, int t) {
    #pragma unroll
    for (int kc = 0; kc < KC; kc++) {
        const int kw = kc * 8;
        u32 ah[2][4], al[2][4];
        #pragma unroll
        for (int i = 0; i < 2; i++) {
            int rb = wm * 32 + i * 16;
            ah[i][0] = Ah[(rb + g) * SW + kw + t];
            ah[i][1] = Ah[(rb + g + 8) * SW + kw + t];
            ah[i][2] = Ah[(rb + g) * SW + kw + t + 4];
            ah[i][3] = Ah[(rb + g + 8) * SW + kw + t + 4];
            al[i][0] = Al[(rb + g) * SW + kw + t];
            al[i][1] = Al[(rb + g + 8) * SW + kw + t];
            al[i][2] = Al[(rb + g) * SW + kw + t + 4];
            al[i][3] = Al[(rb + g + 8) * SW + kw + t + 4];
        }
        #pragma unroll
        for (int j = 0; j < 8; j++) {
            int rb = wn * 64 + j * 8;
            u32 bh[2], bl[2];
            bh[0] = Bh[(rb + g) * SW + kw + t];
            bh[1] = Bh[(rb + g) * SW + kw + t + 4];
            bl[0] = Bl[(rb + g) * SW + kw + t];
            bl[1] = Bl[(rb + g) * SW + kw + t + 4];
            #pragma unroll
            for (int i = 0; i < 2; i++) {
                mma16816(acc[i][j], ah[i], bh);
                mma16816(acc[i][j], ah[i], bl);
                mma16816(acc[i][j], al[i], bh);
            }
        }
    }
}

// fused yz tri-product (half-width): acc[4][4] covers m16 (wm) x n32 (wn quarter)
__device__ __forceinline__ void yz_prod3h(float (&acc)[4][4], u32 xhi, u32 xlo,
                                          u32 ahi, u32 alo, int wm, int wn, int lane) {
    const int q = lane >> 3, r = lane & 7;
    #pragma unroll
    for (int kc = 0; kc < 8; kc++) {
        u32 offA = (u32)((wm * 16 + r + (q & 1) * 8) * 136 + kc * 16 + (q >> 1) * 8) * 2;
        u32 ah[4], al[4];
        asm volatile("ldmatrix.sync.aligned.m8n8.x4.shared.b16 {%0,%1,%2,%3}, [%4];"
            : "=r"(ah[0]), "=r"(ah[1]), "=r"(ah[2]), "=r"(ah[3]) : "r"(xhi + offA));
        asm volatile("ldmatrix.sync.aligned.m8n8.x4.shared.b16 {%0,%1,%2,%3}, [%4];"
            : "=r"(al[0]), "=r"(al[1]), "=r"(al[2]), "=r"(al[3]) : "r"(xlo + offA));
        #pragma unroll
        for (int jp = 0; jp < 2; jp++) {
            u32 offB = (u32)((wn * 32 + jp * 16 + r + (q >> 1) * 8) * 136 + kc * 16 + (q & 1) * 8) * 2;
            u32 bh[4], bl[4];
            asm volatile("ldmatrix.sync.aligned.m8n8.x4.shared.b16 {%0,%1,%2,%3}, [%4];"
                : "=r"(bh[0]), "=r"(bh[1]), "=r"(bh[2]), "=r"(bh[3]) : "r"(ahi + offB));
            asm volatile("ldmatrix.sync.aligned.m8n8.x4.shared.b16 {%0,%1,%2,%3}, [%4];"
                : "=r"(bl[0]), "=r"(bl[1]), "=r"(bl[2]), "=r"(bl[3]) : "r"(alo + offB));
            mma16816(acc[2 * jp],     ah, bh);
            mma16816(acc[2 * jp + 1], ah, bh + 2);
            mma16816(acc[2 * jp],     ah, bl);
            mma16816(acc[2 * jp + 1], ah, bl + 2);
            mma16816(acc[2 * jp],     al, bh);
            mma16816(acc[2 * jp + 1], al, bh + 2);
        }
    }
}

// ---------------- K0: PE table ----------------
__global__ void k_init_pe() {
    int s = threadIdx.x;
    int p0 = s >> 5, p1 = s & 31;
    int j = p1 >> 1;
    float freq = powf(1000.0f, -(float)j * (1.0f / 64.0f));
    float arg = 3.14159265358979323846f * (float)p0 * freq;
    g_pe[s] = (p1 & 1) ? cosf(arg) : sinf(arg);
}

// ---------------- K1: A[d][e] + u[d], w[d] ----------------
__global__ void k_prep(const float* __restrict__ W, const float* __restrict__ b) {
    __shared__ float wqd[128];
    __shared__ float wkd[128];
    __shared__ float red[128];
    int d = blockIdx.x, e = threadIdx.x;
    wqd[e] = W[384 * e + d];
    wkd[e] = W[384 * e + 128 + d];
    __syncthreads();
    float acc = 0.f;
    #pragma unroll 4
    for (int g = 0; g < 128; g++) acc += wqd[g] * W[384 * g + 128 + e];
    g_A[d * 128 + e] = acc;

    red[e] = wqd[e] * b[3 * e + 1];
    __syncthreads();
    #pragma unroll
    for (int st = 64; st > 0; st >>= 1) { if (e < st) red[e] += red[e + st]; __syncthreads(); }
    if (e == 0) g_u[d] = red[0];
    __syncthreads();
    red[e] = wkd[e] * b[3 * e];
    __syncthreads();
    #pragma unroll
    for (int st = 64; st > 0; st >>= 1) { if (e < st) red[e] += red[e + st]; __syncthreads(); }
    if (e == 0) g_w[d] = red[0];
}

// ---------------- K1b: padded bf16 operand images ----------------
__global__ void k_prepA(const float* __restrict__ W) {
    int e = blockIdx.x, d = threadIdx.x;
    float a = g_A[d * 128 + e];
    __nv_bfloat16 h = __float2bfloat16(a);
    __nv_bfloat16 l = __float2bfloat16(a - __bfloat162float(h));
    g_Aophi[e * 136 + d] = h;
    g_Aoplo[e * 136 + d] = l;
    float wv = W[384 * e + 256 + d];
    __nv_bfloat16 hw = __float2bfloat16(wv);
    __nv_bfloat16 lw = __float2bfloat16(wv - __bfloat162float(hw));
    g_Wvophi[e * 136 + d] = hw;
    g_Wvoplo[e * 136 + d] = lw;
}

__global__ void k_csum() {
    int i = blockIdx.x * 256 + threadIdx.x;
    float s = 0.f;
    #pragma unroll
    for (int ck = 0; ck < 16; ck++) s += g_cpart[ck * 16384 + i];
    g_c[i] = s;
}
__global__ void k_ab(const float* __restrict__ b) {
    __shared__ float red[128];
    int n = threadIdx.x;
    float a = 0.f, bb = 0.f;
    #pragma unroll 4
    for (int d = 0; d < 128; d++) {
        float cv = g_c[n * 128 + d];
        a  += cv * g_u[d];
        bb += cv * g_w[d];
    }
    g_alpha[n] = a;
    g_beta[n]  = bb;
    g_bv[n] = b[3 * n + 2];
    red[n] = b[3 * n] * b[3 * n + 1];
    __syncthreads();
    #pragma unroll
    for (int st = 64; st > 0; st >>= 1) { if (n < st) red[n] += red[n + st]; __syncthreads(); }
    if (n == 0) g_gamma = 1024.0f * red[0];
}

// ---------------- K5: k_yz — Y = (pe X) Aop^T (e-split), Z = pe X, + c-partials ----------------
// grid (2048, 2): x = 64-row tile, y = 64-col e-half. 256 thr, 3 blocks/SM.
// smem: Xhi[64][136] @0 | Xlo @17408 | Ahalf_hi @34816 | Ahalf_lo @52224 | redc @69632 (4096) = 73728
__global__ void __launch_bounds__(256, 3) k_yz(const float* __restrict__ X) {
    extern __shared__ __align__(16) unsigned char sm[];
    u32 smb = smem_u32(sm);
    float* redc = (float*)(sm + 69632);
    const int tid = threadIdx.x;
    const int rbase = blockIdx.x * 64;
    const int ebase = blockIdx.y * 64;

    for (int i = tid; i < 1088; i += 256) {   // 64 rows x 17 uint4
        cp16(smb + 34816 + i * 16, ((const uint4*)g_Aophi) + ebase * 17 + i);
        cp16(smb + 52224 + i * 16, ((const uint4*)g_Aoplo) + ebase * 17 + i);
    }
    cp_commit();

    float csum[4] = {0.f, 0.f, 0.f, 0.f};
    #pragma unroll
    for (int i = 0; i < 8; i++) {
        int idx = tid + i * 256;
        int row = idx >> 5, jc = idx & 31;
        int r = rbase + row;
        float p = g_pe[r & 1023];
        float4 v = *(const float4*)(X + (size_t)r * 128 + jc * 4);
        float z0 = v.x * p, z1 = v.y * p, z2 = v.z * p, z3 = v.w * p;
        csum[0] += z0; csum[1] += z1; csum[2] += z2; csum[3] += z3;
        u32 h0, l0, h1, l1;
        pack_hilo(z0, z1, h0, l0);
        pack_hilo(z2, z3, h1, l1);
        *(uint2*)(sm + (u32)(row * 272 + jc * 8))         = make_uint2(h0, h1);
        *(uint2*)(sm + 17408 + (u32)(row * 272 + jc * 8)) = make_uint2(l0, l1);
        if (blockIdx.y == 0) {
            *(uint2*)(g_Zhi + (size_t)r * 128 + jc * 4) = make_uint2(h0, h1);
            *(uint2*)(g_Zlo + (size_t)r * 128 + jc * 4) = make_uint2(l0, l1);
        }
    }
    if (blockIdx.y == 0) {
        int grp = tid >> 5, jc = tid & 31;
        *(float4*)(redc + grp * 128 + jc * 4) = make_float4(csum[0], csum[1], csum[2], csum[3]);
    }
    cp_wait<0>();
    __syncthreads();
    if (blockIdx.y == 0 && tid < 128) {
        float t0 = (redc[0 * 128 + tid] + redc[1 * 128 + tid]) + (redc[2 * 128 + tid] + redc[3 * 128 + tid]);
        float t1 = (redc[4 * 128 + tid] + redc[5 * 128 + tid]) + (redc[6 * 128 + tid] + redc[7 * 128 + tid]);
        g_cpart[(blockIdx.x & 15) * 16384 + (blockIdx.x >> 4) * 128 + tid] = t0 + t1;
    }

    const int lane = tid & 31, warp = tid >> 5;
    const int wm = warp >> 1, wn = warp & 1, g = lane >> 2, t = lane & 3;
    float acc[4][4];
    #pragma unroll
    for (int j = 0; j < 4; j++)
        #pragma unroll
        for (int q = 0; q < 4; q++) acc[j][q] = 0.f;

    yz_prod3h(acc, smb, smb + 17408, smb + 34816, smb + 52224, wm, wn, lane);

    {
        int r0 = rbase + wm * 16 + g;
        #pragma unroll
        for (int j = 0; j < 4; j++) {
            int e0 = ebase + wn * 32 + (j >> 1) * 16 + (j & 1) * 8 + 2 * t;
            u32 h, l;
            pack_hilo(acc[j][0], acc[j][1], h, l);
            *(u32*)(g_Yhi + (size_t)r0 * 128 + e0) = h;
            *(u32*)(g_Ylo + (size_t)r0 * 128 + e0) = l;
            pack_hilo(acc[j][2], acc[j][3], h, l);
            *(u32*)(g_Yhi + (size_t)(r0 + 8) * 128 + e0) = h;
            *(u32*)(g_Ylo + (size_t)(r0 + 8) * 128 + e0) = l;
        }
    }
}

// ---------------- K6: k_sc — score partials = Y . Z^T (split-K 256, single-buffer) ----------------
// smem: Yhi @0 | Ylo @18432 | Zhi @36864 | Zlo @55296 = 73728 (2-3 blocks/SM)
__global__ void __launch_bounds__(256, 2) k_sc() {
    extern __shared__ __align__(16) unsigned char sm[];
    u32 smb = smem_u32(sm);
    const int tid = threadIdx.x;

    const int lane = tid & 31, warp = tid >> 5;
    const int wm = warp >> 1, wn = warp & 1, g = lane >> 2, t = lane & 3;

    float acc[2][8][4];
    #pragma unroll
    for (int i = 0; i < 2; i++)
        #pragma unroll
        for (int j = 0; j < 8; j++)
            #pragma unroll
            for (int q = 0; q < 4; q++) acc[i][j][q] = 0.f;

    for (int it = 0; it < 8; it++) {
        size_t c0 = (size_t)blockIdx.x * 512 + (size_t)it * 64;
        #pragma unroll
        for (int q = 0; q < 4; q++) {
            int idx = tid + q * 256;
            int row = idx >> 3, jc = idx & 7;
            u32 d = smb + row * 144 + jc * 16;
            size_t go = (size_t)row * 131072 + c0 + (size_t)jc * 8;
            cp16(d,          g_Yhi + go);
            cp16(d + 18432,  g_Ylo + go);
            cp16(d + 36864,  g_Zhi + go);
            cp16(d + 55296,  g_Zlo + go);
        }
        cp_commit();
        cp_wait<0>();
        __syncthreads();
        gemm_prod3<4, 36>(acc, (const u32*)(sm), (const u32*)(sm + 18432),
                          (const u32*)(sm + 36864), (const u32*)(sm + 55296),
                          wm, wn, g, t);
        __syncthreads();
    }

    float* outp = g_spart + (size_t)blockIdx.x * 16384;
    #pragma unroll
    for (int i = 0; i < 2; i++) {
        int n0 = wm * 32 + i * 16 + g;
        #pragma unroll
        for (int j = 0; j < 8; j++) {
            int m0 = wn * 64 + j * 8 + 2 * t;
            *(float2*)(outp + n0 * 128 + m0)       = make_float2(acc[i][j][0], acc[i][j][1]);
            *(float2*)(outp + (n0 + 8) * 128 + m0) = make_float2(acc[i][j][2], acc[i][j][3]);
        }
    }
}

// ---------------- K7: reduce 256 partials + alpha/beta/gamma (grid 64 x 64) ----------------
__global__ void k_reduce() {
    int f = blockIdx.x * 64 + threadIdx.x;
    float4 a0 = make_float4(0.f, 0.f, 0.f, 0.f), a1 = a0, a2 = a0, a3 = a0;
    for (int p = 0; p < 256; p += 4) {
        float4 v0 = *(const float4*)(g_spart + (size_t)(p + 0) * 16384 + 4 * f);
        float4 v1 = *(const float4*)(g_spart + (size_t)(p + 1) * 16384 + 4 * f);
        float4 v2 = *(const float4*)(g_spart + (size_t)(p + 2) * 16384 + 4 * f);
        float4 v3 = *(const float4*)(g_spart + (size_t)(p + 3) * 16384 + 4 * f);
        a0.x += v0.x; a0.y += v0.y; a0.z += v0.z; a0.w += v0.w;
        a1.x += v1.x; a1.y += v1.y; a1.z += v1.z; a1.w += v1.w;
        a2.x += v2.x; a2.y += v2.y; a2.z += v2.z; a2.w += v2.w;
        a3.x += v3.x; a3.y += v3.y; a3.z += v3.z; a3.w += v3.w;
    }
    float4 tot = make_float4((a0.x + a1.x) + (a2.x + a3.x), (a0.y + a1.y) + (a2.y + a3.y),
                             (a0.z + a1.z) + (a2.z + a3.z), (a0.w + a1.w) + (a2.w + a3.w));
    int n = f >> 5;
    int m0 = (4 * f) & 127;
    float al = g_alpha[n], gm = g_gamma;
    float4 be = *(const float4*)(g_beta + m0);
    *(float4*)(g_scores + 4 * f) = make_float4(tot.x + al + be.x + gm, tot.y + al + be.y + gm,
                                               tot.z + al + be.z + gm, tot.w + al + be.w + gm);
}

// ---------------- K8: parallel softmax → attn hi/lo images ----------------
__global__ void k_softmax() {
    __shared__ float red[128];
    int n = blockIdx.x, j = threadIdx.x;
    const float rs = 0.0883883476483184405f;
    float v = g_scores[n * 128 + j] * rs;
    red[j] = v;
    __syncthreads();
    #pragma unroll
    for (int st = 64; st > 0; st >>= 1) { if (j < st) red[j] = fmaxf(red[j], red[j + st]); __syncthreads(); }
    float m = red[0];
    __syncthreads();
    float e = expf(v - m);
    red[j] = e;
    __syncthreads();
    #pragma unroll
    for (int st = 64; st > 0; st >>= 1) { if (j < st) red[j] += red[j + st]; __syncthreads(); }
    float a = e / red[0];
    __nv_bfloat16 h = __float2bfloat16(a);
    __nv_bfloat16 l = __float2bfloat16(a - __bfloat162float(h));
    g_athi[n * 136 + j] = h;
    g_atlo[n * 136 + j] = l;
}

// ---------------- K9: k_xo — persistent fused (attn @ Z) @ Wv^T + bv ----------------
__global__ void __launch_bounds__(256) k_xo(float* __restrict__ out) {
    extern __shared__ __align__(16) unsigned char sm[];
    u32 smb = smem_u32(sm);
    const int tid = threadIdx.x;
    const int lane = tid & 31, warp = tid >> 5;
    const int wm = warp >> 1, wn = warp & 1, g = lane >> 2, t = lane & 3;
    const int krow_off = (lane & 7) + 8 * ((lane >> 3) & 1);
    const int ncol_off = 8 * (lane >> 4);

    for (int i = tid; i < 2176; i += 256) {
        cp16(smb + i * 16,          ((const uint4*)g_athi) + i);
        cp16(smb + 34816 + i * 16,  ((const uint4*)g_atlo) + i);
        cp16(smb + 139264 + i * 16, ((const uint4*)g_Wvophi) + i);
        cp16(smb + 174080 + i * 16, ((const uint4*)g_Wvoplo) + i);
    }
    cp_commit();

    const u32* Ahi = (const u32*)(sm);
    const u32* Alo = (const u32*)(sm + 34816);
    const u32* Ih = (const u32*)(sm + 69632);
    const u32* Il = (const u32*)(sm + 104448);
    const u32* Wh = (const u32*)(sm + 139264);
    const u32* Wl = (const u32*)(sm + 174080);

    for (int s_blk = blockIdx.x; s_blk < 1024; s_blk += 148) {
        const int cb = s_blk * 128;
        __syncthreads();

        for (int i = tid; i < 2048; i += 256) {
            int row = i >> 4, jc = i & 15;
            u32 d = smb + 69632 + row * 272 + jc * 16;
            size_t go = (size_t)row * 131072 + cb + (size_t)jc * 8;
            cp16(d,         g_Zhi + go);
            cp16(d + 34816, g_Zlo + go);
        }
        cp_commit(); cp_wait<0>(); __syncthreads();

        float acc[2][8][4];
        #pragma unroll
        for (int i = 0; i < 2; i++)
            #pragma unroll
            for (int j = 0; j < 8; j++)
                #pragma unroll
                for (int q = 0; q < 4; q++) acc[i][j][q] = 0.f;

        // phase 1: interm = attn @ Z  (B via ldmatrix.trans; fused)
        #pragma unroll
        for (int kc = 0; kc < 8; kc++) {
            const int kw = kc * 8;
            u32 ah[2][4], al[2][4];
            #pragma unroll
            for (int i = 0; i < 2; i++) {
                int rb = wm * 32 + i * 16;
                ah[i][0] = Ahi[(rb + g) * 68 + kw + t];
                ah[i][1] = Ahi[(rb + g + 8) * 68 + kw + t];
                ah[i][2] = Ahi[(rb + g) * 68 + kw + t + 4];
                ah[i][3] = Ahi[(rb + g + 8) * 68 + kw + t + 4];
                al[i][0] = Alo[(rb + g) * 68 + kw + t];
                al[i][1] = Alo[(rb + g + 8) * 68 + kw + t];
                al[i][2] = Alo[(rb + g) * 68 + kw + t + 4];
                al[i][3] = Alo[(rb + g + 8) * 68 + kw + t + 4];
            }
            u32 zrow = smb + 69632 + (u32)(kc * 16 + krow_off) * 272;
            #pragma unroll
            for (int jp = 0; jp < 4; jp++) {
                u32 addr = zrow + (u32)(wn * 64 + jp * 16 + ncol_off) * 2;
                u32 bh[4], bl[4];
                asm volatile("ldmatrix.sync.aligned.m8n8.x4.trans.shared.b16 {%0,%1,%2,%3}, [%4];"
                    : "=r"(bh[0]), "=r"(bh[1]), "=r"(bh[2]), "=r"(bh[3]) : "r"(addr));
                asm volatile("ldmatrix.sync.aligned.m8n8.x4.trans.shared.b16 {%0,%1,%2,%3}, [%4];"
                    : "=r"(bl[0]), "=r"(bl[1]), "=r"(bl[2]), "=r"(bl[3]) : "r"(addr + 34816));
                #pragma unroll
                for (int i = 0; i < 2; i++) {
                    mma16816(acc[i][2 * jp],     ah[i], bh);
                    mma16816(acc[i][2 * jp + 1], ah[i], bh + 2);
                    mma16816(acc[i][2 * jp],     al[i], bh);
                    mma16816(acc[i][2 * jp + 1], al[i], bh + 2);
                    mma16816(acc[i][2 * jp],     ah[i], bl);
                    mma16816(acc[i][2 * jp + 1], ah[i], bl + 2);
                }
            }
        }

        // repack interm into the Z region as hi/lo [n][136]
        __syncthreads();
        #pragma unroll
        for (int i = 0; i < 2; i++) {
            int nr = wm * 32 + i * 16 + g;
            #pragma unroll
            for (int j = 0; j < 8; j++) {
                int col = wn * 64 + j * 8 + 2 * t;
                u32 h, l;
                pack_hilo(acc[i][j][0], acc[i][j][1], h, l);
                *(u32*)(sm + 69632 + (u32)nr * 272 + col * 2) = h;
                *(u32*)(sm + 104448 + (u32)nr * 272 + col * 2) = l;
                pack_hilo(acc[i][j][2], acc[i][j][3], h, l);
                *(u32*)(sm + 69632 + (u32)(nr + 8) * 272 + col * 2) = h;
                *(u32*)(sm + 104448 + (u32)(nr + 8) * 272 + col * 2) = l;
            }
        }
        __syncthreads();

        // phase 2: out = interm @ Wv^T + bv (fused tri-product)
        #pragma unroll
        for (int i = 0; i < 2; i++)
            #pragma unroll
            for (int j = 0; j < 8; j++)
                #pragma unroll
                for (int q = 0; q < 4; q++) acc[i][j][q] = 0.f;

        gemm_prod3<8, 68>(acc, Ih, Il, Wh, Wl, wm, wn, g, t);

        #pragma unroll
        for (int i = 0; i < 2; i++) {
            int n0 = wm * 32 + i * 16 + g;
            size_t r0 = (size_t)n0 * 1024 + s_blk;
            size_t r1 = (size_t)(n0 + 8) * 1024 + s_blk;
            #pragma unroll
            for (int j = 0; j < 8; j++) {
                int e0 = wn * 64 + j * 8 + 2 * t;
                float2 bp = *(const float2*)(g_bv + e0);
                *(float2*)(out + r0 * 128 + e0) =
                    make_float2(acc[i][j][0] + bp.x, acc[i][j][1] + bp.y);
                *(float2*)(out + r1 * 128 + e0) =
                    make_float2(acc[i][j][2] + bp.x, acc[i][j][3] + bp.y);
            }
        }
    }
}

// ---------------- launch ----------------
extern "C" void kernel_launch(void* const* d_in, const int* in_sizes, int n_in,
                              void* d_out, int out_size) {
    const float* x = nullptr; const float* W = nullptr; const float* b = nullptr;
    for (int i = 0; i < n_in; i++) {
        if      (in_sizes[i] == 16777216) x = (const float*)d_in[i];
        else if (in_sizes[i] == 49152)    W = (const float*)d_in[i];
        else if (in_sizes[i] == 384)      b = (const float*)d_in[i];
    }
    if (!x) x = (const float*)d_in[0];
    if (!W) W = (const float*)d_in[1];
    if (!b) b = (const float*)d_in[2];
    float* out = (float*)d_out;

    cudaFuncSetAttribute(k_yz, cudaFuncAttributeMaxDynamicSharedMemorySize, 73728);
    cudaFuncSetAttribute(k_sc, cudaFuncAttributeMaxDynamicSharedMemorySize, 73728);
    cudaFuncSetAttribute(k_xo, cudaFuncAttributeMaxDynamicSharedMemorySize, 208896);

    k_init_pe<<<1, 1024>>>();
    k_prep<<<128, 128>>>(W, b);
    k_prepA<<<128, 128>>>(W);
    k_yz<<<dim3(2048, 2), 256, 73728>>>(x);
    k_csum<<<64, 256>>>();
    k_ab<<<1, 128>>>(b);
    k_sc<<<256, 256, 73728>>>();
    k_reduce<<<64, 64>>>();
    k_softmax<<<128, 128>>>();
    k_xo<<<148, 256, 208896>>>(out);
}

// round 15
// speedup vs baseline: 1.0685x; 1.0685x over previous
#include <cuda_runtime.h>
#include <cuda_bf16.h>

typedef unsigned long long u64;
typedef unsigned int u32;

// ---------------- scratch ----------------
__device__ float g_spart[256 * 16384];
__device__ float g_scores[16384];
__device__ float g_pe[1024];
__device__ float g_A[16384];             // A[d][e] = sum_g Wq[g,d] Wk[g,e]
__device__ float g_bv[128];
__device__ float g_u[128];
__device__ float g_w[128];
__device__ float g_cpart[16 * 16384];
__device__ float g_c[16384];
__device__ float g_alpha[128];
__device__ float g_beta[128];
__device__ float g_gamma;

// bf16 hi/lo tensors
__device__ __align__(16) __nv_bfloat16 g_Yhi[16777216];
__device__ __align__(16) __nv_bfloat16 g_Ylo[16777216];
__device__ __align__(16) __nv_bfloat16 g_Zhi[16777216];
__device__ __align__(16) __nv_bfloat16 g_Zlo[16777216];
// padded operand images [128][136]
__device__ __align__(16) __nv_bfloat16 g_Aophi[17408];
__device__ __align__(16) __nv_bfloat16 g_Aoplo[17408];
__device__ __align__(16) __nv_bfloat16 g_Wvophi[17408];
__device__ __align__(16) __nv_bfloat16 g_Wvoplo[17408];
__device__ __align__(16) __nv_bfloat16 g_athi[17408];   // attn hi [128][136]
__device__ __align__(16) __nv_bfloat16 g_atlo[17408];   // attn lo

// ---------------- helpers ----------------
__device__ __forceinline__ u32 smem_u32(const void* p) {
    u32 a; asm("{ .reg .u64 t; cvta.to.shared.u64 t, %1; cvt.u32.u64 %0, t; }" : "=r"(a) : "l"(p));
    return a;
}
__device__ __forceinline__ void cp16(u32 dst, const void* src) {
    asm volatile("cp.async.cg.shared.global [%0], [%1], 16;" :: "r"(dst), "l"(src));
}
__device__ __forceinline__ void cp_commit() { asm volatile("cp.async.commit_group;" ::: "memory"); }
template<int N> __device__ __forceinline__ void cp_wait() {
    asm volatile("cp.async.wait_group %0;" :: "n"(N) : "memory");
}

__device__ __forceinline__ void mma16816(float* c, const u32* a, const u32* b) {
    asm volatile("mma.sync.aligned.m16n8k16.row.col.f32.bf16.bf16.f32 "
        "{%0,%1,%2,%3}, {%4,%5,%6,%7}, {%8,%9}, {%0,%1,%2,%3};"
        : "+f"(c[0]), "+f"(c[1]), "+f"(c[2]), "+f"(c[3])
        : "r"(a[0]), "r"(a[1]), "r"(a[2]), "r"(a[3]), "r"(b[0]), "r"(b[1]));
}

__device__ __forceinline__ void pack_hilo(float a, float b, u32& hp, u32& lp) {
    __nv_bfloat16 ha = __float2bfloat16(a), hb = __float2bfloat16(b);
    float ra = a - __bfloat162float(ha), rb = b - __bfloat162float(hb);
    __nv_bfloat16 la = __float2bfloat16(ra), lb = __float2bfloat16(rb);
    hp = (u32)__bfloat16_as_ushort(ha) | ((u32)__bfloat16_as_ushort(hb) << 16);
    lp = (u32)__bfloat16_as_ushort(la) | ((u32)__bfloat16_as_ushort(lb) << 16);
}

// fused tri-product: C += Ah*Bh^T + Ah*Bl^T + Al*Bh^T  (fragments loaded once)
template<int KC, int SW>
__device__ __forceinline__ void gemm_prod3(float (&acc)[2][8][4],
                                           const u32* Ah, const u32* Al,
                                           const u32* Bh, const u32* Bl,
                                           int wm, int wn, int g, int t) {
    #pragma unroll
    for (int kc = 0; kc < KC; kc++) {
        const int kw = kc * 8;
        u32 ah[2][4], al[2][4];
        #pragma unroll
        for (int i = 0; i < 2; i++) {
            int rb = wm * 32 + i * 16;
            ah[i][0] = Ah[(rb + g) * SW + kw + t];
            ah[i][1] = Ah[(rb + g + 8) * SW + kw + t];
            ah[i][2] = Ah[(rb + g) * SW + kw + t + 4];
            ah[i][3] = Ah[(rb + g + 8) * SW + kw + t + 4];
            al[i][0] = Al[(rb + g) * SW + kw + t];
            al[i][1] = Al[(rb + g + 8) * SW + kw + t];
            al[i][2] = Al[(rb + g) * SW + kw + t + 4];
            al[i][3] = Al[(rb + g + 8) * SW + kw + t + 4];
        }
        #pragma unroll
        for (int j = 0; j < 8; j++) {
            int rb = wn * 64 + j * 8;
            u32 bh[2], bl[2];
            bh[0] = Bh[(rb + g) * SW + kw + t];
            bh[1] = Bh[(rb + g) * SW + kw + t + 4];
            bl[0] = Bl[(rb + g) * SW + kw + t];
            bl[1] = Bl[(rb + g) * SW + kw + t + 4];
            #pragma unroll
            for (int i = 0; i < 2; i++) {
                mma16816(acc[i][j], ah[i], bh);
                mma16816(acc[i][j], ah[i], bl);
                mma16816(acc[i][j], al[i], bh);
            }
        }
    }
}

// fused yz tri-product via ldmatrix: acc[8][4] covers m16 (wm) x n128
__device__ __forceinline__ void yz_prod3(float (&acc)[8][4], u32 xhi, u32 xlo,
                                         u32 ahi, u32 alo, int wm, int wn, int lane) {
    const int q = lane >> 3, r = lane & 7;
    #pragma unroll
    for (int kc = 0; kc < 8; kc++) {
        u32 offA = (u32)((wm * 16 + r + (q & 1) * 8) * 136 + kc * 16 + (q >> 1) * 8) * 2;
        u32 ah[4], al[4];
        asm volatile("ldmatrix.sync.aligned.m8n8.x4.shared.b16 {%0,%1,%2,%3}, [%4];"
            : "=r"(ah[0]), "=r"(ah[1]), "=r"(ah[2]), "=r"(ah[3]) : "r"(xhi + offA));
        asm volatile("ldmatrix.sync.aligned.m8n8.x4.shared.b16 {%0,%1,%2,%3}, [%4];"
            : "=r"(al[0]), "=r"(al[1]), "=r"(al[2]), "=r"(al[3]) : "r"(xlo + offA));
        #pragma unroll
        for (int jp = 0; jp < 4; jp++) {
            u32 offB = (u32)((wn * 64 + jp * 16 + r + (q >> 1) * 8) * 136 + kc * 16 + (q & 1) * 8) * 2;
            u32 bh[4], bl[4];
            asm volatile("ldmatrix.sync.aligned.m8n8.x4.shared.b16 {%0,%1,%2,%3}, [%4];"
                : "=r"(bh[0]), "=r"(bh[1]), "=r"(bh[2]), "=r"(bh[3]) : "r"(ahi + offB));
            asm volatile("ldmatrix.sync.aligned.m8n8.x4.shared.b16 {%0,%1,%2,%3}, [%4];"
                : "=r"(bl[0]), "=r"(bl[1]), "=r"(bl[2]), "=r"(bl[3]) : "r"(alo + offB));
            mma16816(acc[2 * jp],     ah, bh);
            mma16816(acc[2 * jp + 1], ah, bh + 2);
            mma16816(acc[2 * jp],     ah, bl);
            mma16816(acc[2 * jp + 1], ah, bl + 2);
            mma16816(acc[2 * jp],     al, bh);
            mma16816(acc[2 * jp + 1], al, bh + 2);
        }
    }
}

// ---------------- K0: PE table ----------------
__global__ void k_init_pe() {
    int s = threadIdx.x;
    int p0 = s >> 5, p1 = s & 31;
    int j = p1 >> 1;
    float freq = powf(1000.0f, -(float)j * (1.0f / 64.0f));
    float arg = 3.14159265358979323846f * (float)p0 * freq;
    g_pe[s] = (p1 & 1) ? cosf(arg) : sinf(arg);
}

// ---------------- K1: A[d][e] + u[d], w[d] ----------------
__global__ void k_prep(const float* __restrict__ W, const float* __restrict__ b) {
    __shared__ float wqd[128];
    __shared__ float wkd[128];
    __shared__ float red[128];
    int d = blockIdx.x, e = threadIdx.x;
    wqd[e] = W[384 * e + d];
    wkd[e] = W[384 * e + 128 + d];
    __syncthreads();
    float acc = 0.f;
    #pragma unroll 4
    for (int g = 0; g < 128; g++) acc += wqd[g] * W[384 * g + 128 + e];
    g_A[d * 128 + e] = acc;

    red[e] = wqd[e] * b[3 * e + 1];
    __syncthreads();
    #pragma unroll
    for (int st = 64; st > 0; st >>= 1) { if (e < st) red[e] += red[e + st]; __syncthreads(); }
    if (e == 0) g_u[d] = red[0];
    __syncthreads();
    red[e] = wkd[e] * b[3 * e];
    __syncthreads();
    #pragma unroll
    for (int st = 64; st > 0; st >>= 1) { if (e < st) red[e] += red[e + st]; __syncthreads(); }
    if (e == 0) g_w[d] = red[0];
}

// ---------------- K1b: padded bf16 operand images ----------------
__global__ void k_prepA(const float* __restrict__ W) {
    int e = blockIdx.x, d = threadIdx.x;
    float a = g_A[d * 128 + e];
    __nv_bfloat16 h = __float2bfloat16(a);
    __nv_bfloat16 l = __float2bfloat16(a - __bfloat162float(h));
    g_Aophi[e * 136 + d] = h;
    g_Aoplo[e * 136 + d] = l;
    float wv = W[384 * e + 256 + d];
    __nv_bfloat16 hw = __float2bfloat16(wv);
    __nv_bfloat16 lw = __float2bfloat16(wv - __bfloat162float(hw));
    g_Wvophi[e * 136 + d] = hw;
    g_Wvoplo[e * 136 + d] = lw;
}

__global__ void k_csum() {
    int i = blockIdx.x * 256 + threadIdx.x;
    float s = 0.f;
    #pragma unroll
    for (int ck = 0; ck < 16; ck++) s += g_cpart[ck * 16384 + i];
    g_c[i] = s;
}
__global__ void k_ab(const float* __restrict__ b) {
    __shared__ float red[128];
    int n = threadIdx.x;
    float a = 0.f, bb = 0.f;
    #pragma unroll 4
    for (int d = 0; d < 128; d++) {
        float cv = g_c[n * 128 + d];
        a  += cv * g_u[d];
        bb += cv * g_w[d];
    }
    g_alpha[n] = a;
    g_beta[n]  = bb;
    g_bv[n] = b[3 * n + 2];
    red[n] = b[3 * n] * b[3 * n + 1];
    __syncthreads();
    #pragma unroll
    for (int st = 64; st > 0; st >>= 1) { if (n < st) red[n] += red[n + st]; __syncthreads(); }
    if (n == 0) g_gamma = 1024.0f * red[0];
}

// ---------------- K5: k_yz — Y = (pe X) Aop^T, Z = pe X, + c-partials (R13 config) ----------------
// grid 2048 (64 rows each), 256 thr, 2 blocks/SM.
// smem: Xhi[64][136] @0 | Xlo @17408 | Ahi @34816 | Alo @69632 | redc @104448 (4096)
__global__ void __launch_bounds__(256, 2) k_yz(const float* __restrict__ X) {
    extern __shared__ __align__(16) unsigned char sm[];
    u32 smb = smem_u32(sm);
    float* redc = (float*)(sm + 104448);
    const int tid = threadIdx.x;
    const int rbase = blockIdx.x * 64;

    for (int i = tid; i < 2176; i += 256) {
        cp16(smb + 34816 + i * 16, ((const uint4*)g_Aophi) + i);
        cp16(smb + 69632 + i * 16, ((const uint4*)g_Aoplo) + i);
    }
    cp_commit();

    float csum[4] = {0.f, 0.f, 0.f, 0.f};
    #pragma unroll
    for (int i = 0; i < 8; i++) {
        int idx = tid + i * 256;
        int row = idx >> 5, jc = idx & 31;
        int r = rbase + row;
        float p = g_pe[r & 1023];
        float4 v = *(const float4*)(X + (size_t)r * 128 + jc * 4);
        float z0 = v.x * p, z1 = v.y * p, z2 = v.z * p, z3 = v.w * p;
        csum[0] += z0; csum[1] += z1; csum[2] += z2; csum[3] += z3;
        u32 h0, l0, h1, l1;
        pack_hilo(z0, z1, h0, l0);
        pack_hilo(z2, z3, h1, l1);
        *(uint2*)(sm + (u32)(row * 272 + jc * 8))         = make_uint2(h0, h1);
        *(uint2*)(sm + 17408 + (u32)(row * 272 + jc * 8)) = make_uint2(l0, l1);
        *(uint2*)(g_Zhi + (size_t)r * 128 + jc * 4) = make_uint2(h0, h1);
        *(uint2*)(g_Zlo + (size_t)r * 128 + jc * 4) = make_uint2(l0, l1);
    }
    {
        int grp = tid >> 5, jc = tid & 31;
        *(float4*)(redc + grp * 128 + jc * 4) = make_float4(csum[0], csum[1], csum[2], csum[3]);
    }
    cp_wait<0>();
    __syncthreads();
    if (tid < 128) {
        float t0 = (redc[0 * 128 + tid] + redc[1 * 128 + tid]) + (redc[2 * 128 + tid] + redc[3 * 128 + tid]);
        float t1 = (redc[4 * 128 + tid] + redc[5 * 128 + tid]) + (redc[6 * 128 + tid] + redc[7 * 128 + tid]);
        g_cpart[(blockIdx.x & 15) * 16384 + (blockIdx.x >> 4) * 128 + tid] = t0 + t1;
    }

    const int lane = tid & 31, warp = tid >> 5;
    const int wm = warp >> 1, wn = warp & 1, g = lane >> 2, t = lane & 3;
    float acc[8][4];
    #pragma unroll
    for (int j = 0; j < 8; j++)
        #pragma unroll
        for (int q = 0; q < 4; q++) acc[j][q] = 0.f;

    yz_prod3(acc, smb, smb + 17408, smb + 34816, smb + 69632, wm, wn, lane);

    {
        int r0 = rbase + wm * 16 + g;
        #pragma unroll
        for (int j = 0; j < 8; j++) {
            int e0 = wn * 64 + (j >> 1) * 16 + (j & 1) * 8 + 2 * t;
            u32 h, l;
            pack_hilo(acc[j][0], acc[j][1], h, l);
            *(u32*)(g_Yhi + (size_t)r0 * 128 + e0) = h;
            *(u32*)(g_Ylo + (size_t)r0 * 128 + e0) = l;
            pack_hilo(acc[j][2], acc[j][3], h, l);
            *(u32*)(g_Yhi + (size_t)(r0 + 8) * 128 + e0) = h;
            *(u32*)(g_Ylo + (size_t)(r0 + 8) * 128 + e0) = l;
        }
    }
}

// ---------------- K6: k_sc — score partials = Y . Z^T (split-K 256, single-buffer, 2/SM) ----------------
// smem: Yhi @0 | Ylo @18432 | Zhi @36864 | Zlo @55296 = 73728
__global__ void __launch_bounds__(256, 2) k_sc() {
    extern __shared__ __align__(16) unsigned char sm[];
    u32 smb = smem_u32(sm);
    const int tid = threadIdx.x;

    const int lane = tid & 31, warp = tid >> 5;
    const int wm = warp >> 1, wn = warp & 1, g = lane >> 2, t = lane & 3;

    float acc[2][8][4];
    #pragma unroll
    for (int i = 0; i < 2; i++)
        #pragma unroll
        for (int j = 0; j < 8; j++)
            #pragma unroll
            for (int q = 0; q < 4; q++) acc[i][j][q] = 0.f;

    for (int it = 0; it < 8; it++) {
        size_t c0 = (size_t)blockIdx.x * 512 + (size_t)it * 64;
        #pragma unroll
        for (int q = 0; q < 4; q++) {
            int idx = tid + q * 256;
            int row = idx >> 3, jc = idx & 7;
            u32 d = smb + row * 144 + jc * 16;
            size_t go = (size_t)row * 131072 + c0 + (size_t)jc * 8;
            cp16(d,          g_Yhi + go);
            cp16(d + 18432,  g_Ylo + go);
            cp16(d + 36864,  g_Zhi + go);
            cp16(d + 55296,  g_Zlo + go);
        }
        cp_commit();
        cp_wait<0>();
        __syncthreads();
        gemm_prod3<4, 36>(acc, (const u32*)(sm), (const u32*)(sm + 18432),
                          (const u32*)(sm + 36864), (const u32*)(sm + 55296),
                          wm, wn, g, t);
        __syncthreads();
    }

    float* outp = g_spart + (size_t)blockIdx.x * 16384;
    #pragma unroll
    for (int i = 0; i < 2; i++) {
        int n0 = wm * 32 + i * 16 + g;
        #pragma unroll
        for (int j = 0; j < 8; j++) {
            int m0 = wn * 64 + j * 8 + 2 * t;
            *(float2*)(outp + n0 * 128 + m0)       = make_float2(acc[i][j][0], acc[i][j][1]);
            *(float2*)(outp + (n0 + 8) * 128 + m0) = make_float2(acc[i][j][2], acc[i][j][3]);
        }
    }
}

// ---------------- K7: reduce 256 partials + alpha/beta/gamma (grid 64 x 64) ----------------
__global__ void k_reduce() {
    int f = blockIdx.x * 64 + threadIdx.x;
    float4 a0 = make_float4(0.f, 0.f, 0.f, 0.f), a1 = a0, a2 = a0, a3 = a0;
    for (int p = 0; p < 256; p += 4) {
        float4 v0 = *(const float4*)(g_spart + (size_t)(p + 0) * 16384 + 4 * f);
        float4 v1 = *(const float4*)(g_spart + (size_t)(p + 1) * 16384 + 4 * f);
        float4 v2 = *(const float4*)(g_spart + (size_t)(p + 2) * 16384 + 4 * f);
        float4 v3 = *(const float4*)(g_spart + (size_t)(p + 3) * 16384 + 4 * f);
        a0.x += v0.x; a0.y += v0.y; a0.z += v0.z; a0.w += v0.w;
        a1.x += v1.x; a1.y += v1.y; a1.z += v1.z; a1.w += v1.w;
        a2.x += v2.x; a2.y += v2.y; a2.z += v2.z; a2.w += v2.w;
        a3.x += v3.x; a3.y += v3.y; a3.z += v3.z; a3.w += v3.w;
    }
    float4 tot = make_float4((a0.x + a1.x) + (a2.x + a3.x), (a0.y + a1.y) + (a2.y + a3.y),
                             (a0.z + a1.z) + (a2.z + a3.z), (a0.w + a1.w) + (a2.w + a3.w));
    int n = f >> 5;
    int m0 = (4 * f) & 127;
    float al = g_alpha[n], gm = g_gamma;
    float4 be = *(const float4*)(g_beta + m0);
    *(float4*)(g_scores + 4 * f) = make_float4(tot.x + al + be.x + gm, tot.y + al + be.y + gm,
                                               tot.z + al + be.z + gm, tot.w + al + be.w + gm);
}

// ---------------- K8: parallel softmax → attn hi/lo images ----------------
__global__ void k_softmax() {
    __shared__ float red[128];
    int n = blockIdx.x, j = threadIdx.x;
    const float rs = 0.0883883476483184405f;
    float v = g_scores[n * 128 + j] * rs;
    red[j] = v;
    __syncthreads();
    #pragma unroll
    for (int st = 64; st > 0; st >>= 1) { if (j < st) red[j] = fmaxf(red[j], red[j + st]); __syncthreads(); }
    float m = red[0];
    __syncthreads();
    float e = expf(v - m);
    red[j] = e;
    __syncthreads();
    #pragma unroll
    for (int st = 64; st > 0; st >>= 1) { if (j < st) red[j] += red[j + st]; __syncthreads(); }
    float a = e / red[0];
    __nv_bfloat16 h = __float2bfloat16(a);
    __nv_bfloat16 l = __float2bfloat16(a - __bfloat162float(h));
    g_athi[n * 136 + j] = h;
    g_atlo[n * 136 + j] = l;
}

// ---------------- K9: k_xo — persistent fused (attn @ Z) @ Wv^T + bv ----------------
__global__ void __launch_bounds__(256) k_xo(float* __restrict__ out) {
    extern __shared__ __align__(16) unsigned char sm[];
    u32 smb = smem_u32(sm);
    const int tid = threadIdx.x;
    const int lane = tid & 31, warp = tid >> 5;
    const int wm = warp >> 1, wn = warp & 1, g = lane >> 2, t = lane & 3;
    const int krow_off = (lane & 7) + 8 * ((lane >> 3) & 1);
    const int ncol_off = 8 * (lane >> 4);

    for (int i = tid; i < 2176; i += 256) {
        cp16(smb + i * 16,          ((const uint4*)g_athi) + i);
        cp16(smb + 34816 + i * 16,  ((const uint4*)g_atlo) + i);
        cp16(smb + 139264 + i * 16, ((const uint4*)g_Wvophi) + i);
        cp16(smb + 174080 + i * 16, ((const uint4*)g_Wvoplo) + i);
    }
    cp_commit();

    const u32* Ahi = (const u32*)(sm);
    const u32* Alo = (const u32*)(sm + 34816);
    const u32* Ih = (const u32*)(sm + 69632);
    const u32* Il = (const u32*)(sm + 104448);
    const u32* Wh = (const u32*)(sm + 139264);
    const u32* Wl = (const u32*)(sm + 174080);

    for (int s_blk = blockIdx.x; s_blk < 1024; s_blk += 148) {
        const int cb = s_blk * 128;
        __syncthreads();

        for (int i = tid; i < 2048; i += 256) {
            int row = i >> 4, jc = i & 15;
            u32 d = smb + 69632 + row * 272 + jc * 16;
            size_t go = (size_t)row * 131072 + cb + (size_t)jc * 8;
            cp16(d,         g_Zhi + go);
            cp16(d + 34816, g_Zlo + go);
        }
        cp_commit(); cp_wait<0>(); __syncthreads();

        float acc[2][8][4];
        #pragma unroll
        for (int i = 0; i < 2; i++)
            #pragma unroll
            for (int j = 0; j < 8; j++)
                #pragma unroll
                for (int q = 0; q < 4; q++) acc[i][j][q] = 0.f;

        // phase 1: interm = attn @ Z  (B via ldmatrix.trans; fused)
        #pragma unroll
        for (int kc = 0; kc < 8; kc++) {
            const int kw = kc * 8;
            u32 ah[2][4], al[2][4];
            #pragma unroll
            for (int i = 0; i < 2; i++) {
                int rb = wm * 32 + i * 16;
                ah[i][0] = Ahi[(rb + g) * 68 + kw + t];
                ah[i][1] = Ahi[(rb + g + 8) * 68 + kw + t];
                ah[i][2] = Ahi[(rb + g) * 68 + kw + t + 4];
                ah[i][3] = Ahi[(rb + g + 8) * 68 + kw + t + 4];
                al[i][0] = Alo[(rb + g) * 68 + kw + t];
                al[i][1] = Alo[(rb + g + 8) * 68 + kw + t];
                al[i][2] = Alo[(rb + g) * 68 + kw + t + 4];
                al[i][3] = Alo[(rb + g + 8) * 68 + kw + t + 4];
            }
            u32 zrow = smb + 69632 + (u32)(kc * 16 + krow_off) * 272;
            #pragma unroll
            for (int jp = 0; jp < 4; jp++) {
                u32 addr = zrow + (u32)(wn * 64 + jp * 16 + ncol_off) * 2;
                u32 bh[4], bl[4];
                asm volatile("ldmatrix.sync.aligned.m8n8.x4.trans.shared.b16 {%0,%1,%2,%3}, [%4];"
                    : "=r"(bh[0]), "=r"(bh[1]), "=r"(bh[2]), "=r"(bh[3]) : "r"(addr));
                asm volatile("ldmatrix.sync.aligned.m8n8.x4.trans.shared.b16 {%0,%1,%2,%3}, [%4];"
                    : "=r"(bl[0]), "=r"(bl[1]), "=r"(bl[2]), "=r"(bl[3]) : "r"(addr + 34816));
                #pragma unroll
                for (int i = 0; i < 2; i++) {
                    mma16816(acc[i][2 * jp],     ah[i], bh);
                    mma16816(acc[i][2 * jp + 1], ah[i], bh + 2);
                    mma16816(acc[i][2 * jp],     al[i], bh);
                    mma16816(acc[i][2 * jp + 1], al[i], bh + 2);
                    mma16816(acc[i][2 * jp],     ah[i], bl);
                    mma16816(acc[i][2 * jp + 1], ah[i], bl + 2);
                }
            }
        }

        // repack interm into the Z region as hi/lo [n][136]
        __syncthreads();
        #pragma unroll
        for (int i = 0; i < 2; i++) {
            int nr = wm * 32 + i * 16 + g;
            #pragma unroll
            for (int j = 0; j < 8; j++) {
                int col = wn * 64 + j * 8 + 2 * t;
                u32 h, l;
                pack_hilo(acc[i][j][0], acc[i][j][1], h, l);
                *(u32*)(sm + 69632 + (u32)nr * 272 + col * 2) = h;
                *(u32*)(sm + 104448 + (u32)nr * 272 + col * 2) = l;
                pack_hilo(acc[i][j][2], acc[i][j][3], h, l);
                *(u32*)(sm + 69632 + (u32)(nr + 8) * 272 + col * 2) = h;
                *(u32*)(sm + 104448 + (u32)(nr + 8) * 272 + col * 2) = l;
            }
        }
        __syncthreads();

        // phase 2: out = interm @ Wv^T + bv (fused tri-product)
        #pragma unroll
        for (int i = 0; i < 2; i++)
            #pragma unroll
            for (int j = 0; j < 8; j++)
                #pragma unroll
                for (int q = 0; q < 4; q++) acc[i][j][q] = 0.f;

        gemm_prod3<8, 68>(acc, Ih, Il, Wh, Wl, wm, wn, g, t);

        #pragma unroll
        for (int i = 0; i < 2; i++) {
            int n0 = wm * 32 + i * 16 + g;
            size_t r0 = (size_t)n0 * 1024 + s_blk;
            size_t r1 = (size_t)(n0 + 8) * 1024 + s_blk;
            #pragma unroll
            for (int j = 0; j < 8; j++) {
                int e0 = wn * 64 + j * 8 + 2 * t;
                float2 bp = *(const float2*)(g_bv + e0);
                *(float2*)(out + r0 * 128 + e0) =
                    make_float2(acc[i][j][0] + bp.x, acc[i][j][1] + bp.y);
                *(float2*)(out + r1 * 128 + e0) =
                    make_float2(acc[i][j][2] + bp.x, acc[i][j][3] + bp.y);
            }
        }
    }
}

// ---------------- launch ----------------
extern "C" void kernel_launch(void* const* d_in, const int* in_sizes, int n_in,
                              void* d_out, int out_size) {
    const float* x = nullptr; const float* W = nullptr; const float* b = nullptr;
    for (int i = 0; i < n_in; i++) {
        if      (in_sizes[i] == 16777216) x = (const float*)d_in[i];
        else if (in_sizes[i] == 49152)    W = (const float*)d_in[i];
        else if (in_sizes[i] == 384)      b = (const float*)d_in[i];
    }
    if (!x) x = (const float*)d_in[0];
    if (!W) W = (const float*)d_in[1];
    if (!b) b = (const float*)d_in[2];
    float* out = (float*)d_out;

    cudaFuncSetAttribute(k_yz, cudaFuncAttributeMaxDynamicSharedMemorySize, 108544);
    cudaFuncSetAttribute(k_sc, cudaFuncAttributeMaxDynamicSharedMemorySize, 73728);
    cudaFuncSetAttribute(k_xo, cudaFuncAttributeMaxDynamicSharedMemorySize, 208896);

    k_init_pe<<<1, 1024>>>();
    k_prep<<<128, 128>>>(W, b);
    k_prepA<<<128, 128>>>(W);
    k_yz<<<2048, 256, 108544>>>(x);
    k_csum<<<64, 256>>>();
    k_ab<<<1, 128>>>(b);
    k_sc<<<256, 256, 73728>>>();
    k_reduce<<<64, 64>>>();
    k_softmax<<<128, 128>>>();
    k_xo<<<148, 256, 208896>>>(out);
}